// round 3
// baseline (speedup 1.0000x reference)
#include <cuda_runtime.h>
#include <cstdint>
#include <cstdio>

// ---------------- problem constants ----------------
#define BB_   2
#define LL_   2048
#define EE_   1024
#define HH_   16
#define DH_   64
#define FF_   4096
#define NTOK  (BB_*LL_)          // 4096
#define NZ    (BB_*HH_)          // 32

// ---------------- scratch (device globals; no allocations allowed) ----------------
__device__ float g_xn[NTOK*EE_];
__device__ float g_q [NTOK*EE_];
__device__ float g_k [NTOK*EE_];
__device__ float g_v [NTOK*EE_];
__device__ float g_ctx[NTOK*EE_];
__device__ float g_hidden[NTOK*EE_];
__device__ float g_hn[NTOK*EE_];
__device__ float g_up[(size_t)NTOK*FF_];
__device__ float g_S[(size_t)NZ*LL_*LL_];   // 512 MB attention scores / probs

// ---------------- helpers ----------------
__device__ __forceinline__ uint32_t f2tf(float x){
    uint32_t r; asm("cvt.rna.tf32.f32 %0, %1;" : "=r"(r) : "f"(x)); return r;
}
__device__ __forceinline__ void mma_tf32(float c[4], const uint32_t a[4], const uint32_t b[2]){
    asm volatile("mma.sync.aligned.m16n8k8.row.col.f32.tf32.tf32.f32 "
        "{%0,%1,%2,%3},{%4,%5,%6,%7},{%8,%9},{%0,%1,%2,%3};"
        : "+f"(c[0]), "+f"(c[1]), "+f"(c[2]), "+f"(c[3])
        : "r"(a[0]), "r"(a[1]), "r"(a[2]), "r"(a[3]), "r"(b[0]), "r"(b[1]));
}

// ---------------- LayerNorm: one block per token (E=1024, 256 thr x float4) ----------------
__global__ void ln_k(const float* __restrict__ X, const float* __restrict__ w,
                     const float* __restrict__ bb, float* __restrict__ O)
{
    __shared__ float red[256];
    const int t = threadIdx.x;
    const size_t off = (size_t)blockIdx.x * EE_;
    float4 v = *(const float4*)(X + off + t*4);
    red[t] = v.x + v.y + v.z + v.w;
    __syncthreads();
    #pragma unroll
    for (int s = 128; s > 0; s >>= 1){ if (t < s) red[t] += red[t+s]; __syncthreads(); }
    float mu = red[0] * (1.f/1024.f);
    __syncthreads();
    float d0 = v.x-mu, d1 = v.y-mu, d2 = v.z-mu, d3 = v.w-mu;
    red[t] = d0*d0 + d1*d1 + d2*d2 + d3*d3;
    __syncthreads();
    #pragma unroll
    for (int s = 128; s > 0; s >>= 1){ if (t < s) red[t] += red[t+s]; __syncthreads(); }
    float inv = rsqrtf(red[0] * (1.f/1024.f) + 1e-5f);
    float4 wv = *(const float4*)(w + t*4);
    float4 bv = *(const float4*)(bb + t*4);
    float4 o;
    o.x = d0*inv*wv.x + bv.x;  o.y = d1*inv*wv.y + bv.y;
    o.z = d2*inv*wv.z + bv.z;  o.w = d3*inv*wv.w + bv.w;
    *(float4*)(O + off + t*4) = o;
}

// ---------------- generic GEMM: C[M,N] = epi(A[M,K] @ W[K,N] + bias (+res)) ----------------
// EPI: 0 = bias, 1 = bias + residual, 2 = bias + exact GELU
// SPLIT: 2-term tf32 split (3 MMAs) for ~fp32 operand accuracy
template<int EPI, bool SPLIT>
__global__ void __launch_bounds__(256) gemm_k(
    const float* __restrict__ A, const float* __restrict__ W,
    const float* __restrict__ bias, const float* __restrict__ res,
    float* __restrict__ C, int M, int N, int K)
{
    __shared__ float As[128*36];   // [m][k] padded
    __shared__ float Bs[32*132];   // [k][n] padded
    const int tid  = threadIdx.x;
    const int bm   = blockIdx.y*128, bn = blockIdx.x*128;
    const int lane = tid & 31, warp = tid >> 5;
    const int wm   = warp >> 2, wn = warp & 3;      // 2x4 warp grid, warp tile 64x32
    const int gid  = lane >> 2, t4 = lane & 3;

    float acc[4][4][4];
    #pragma unroll
    for (int a=0;a<4;a++)
    #pragma unroll
    for (int b=0;b<4;b++)
    #pragma unroll
    for (int c=0;c<4;c++) acc[a][b][c] = 0.f;

    const int ar = tid >> 3, ac4 = tid & 7;    // A: rows of 8 float4
    const int br = tid >> 5, bc4 = tid & 31;   // B: rows of 32 float4
    const float* Ap = A + (size_t)(bm+ar)*K + ac4*4;
    const float* Wp = W + (size_t)br*N + bn + bc4*4;

    const int KT = K >> 5;
    float4 aR[4], bR[4];
    #pragma unroll
    for (int i=0;i<4;i++) aR[i] = *(const float4*)(Ap + (size_t)(32*i)*K);
    #pragma unroll
    for (int i=0;i<4;i++) bR[i] = *(const float4*)(Wp + (size_t)(8*i)*N);

    for (int t = 0; t < KT; t++){
        #pragma unroll
        for (int i=0;i<4;i++) *(float4*)(As + (ar+32*i)*36 + ac4*4) = aR[i];
        #pragma unroll
        for (int i=0;i<4;i++) *(float4*)(Bs + (br+8*i)*132 + bc4*4) = bR[i];
        __syncthreads();
        if (t+1 < KT){
            const int k0 = (t+1)*32;
            #pragma unroll
            for (int i=0;i<4;i++) aR[i] = *(const float4*)(Ap + k0 + (size_t)(32*i)*K);
            #pragma unroll
            for (int i=0;i<4;i++) bR[i] = *(const float4*)(Wp + (size_t)(k0+8*i)*N);
        }
        #pragma unroll
        for (int ks=0;ks<4;ks++){
            uint32_t ah[4][4], al[4][4], bh[4][2], bl[4][2];
            #pragma unroll
            for (int mi=0;mi<4;mi++){
                const int r0 = (wm*64 + mi*16 + gid)*36 + ks*8 + t4;
                float x0 = As[r0], x1 = As[r0 + 8*36], x2 = As[r0 + 4], x3 = As[r0 + 8*36 + 4];
                ah[mi][0]=f2tf(x0); ah[mi][1]=f2tf(x1); ah[mi][2]=f2tf(x2); ah[mi][3]=f2tf(x3);
                if (SPLIT){
                    al[mi][0]=f2tf(x0-__uint_as_float(ah[mi][0]));
                    al[mi][1]=f2tf(x1-__uint_as_float(ah[mi][1]));
                    al[mi][2]=f2tf(x2-__uint_as_float(ah[mi][2]));
                    al[mi][3]=f2tf(x3-__uint_as_float(ah[mi][3]));
                }
            }
            #pragma unroll
            for (int ni=0;ni<4;ni++){
                const int c0 = wn*32 + ni*8 + gid;
                float y0 = Bs[(ks*8+t4)*132 + c0];
                float y1 = Bs[(ks*8+t4+4)*132 + c0];
                bh[ni][0]=f2tf(y0); bh[ni][1]=f2tf(y1);
                if (SPLIT){
                    bl[ni][0]=f2tf(y0-__uint_as_float(bh[ni][0]));
                    bl[ni][1]=f2tf(y1-__uint_as_float(bh[ni][1]));
                }
            }
            #pragma unroll
            for (int mi=0;mi<4;mi++)
            #pragma unroll
            for (int ni=0;ni<4;ni++){
                mma_tf32(acc[mi][ni], ah[mi], bh[ni]);
                if (SPLIT){
                    mma_tf32(acc[mi][ni], ah[mi], bl[ni]);
                    mma_tf32(acc[mi][ni], al[mi], bh[ni]);
                }
            }
        }
        __syncthreads();
    }

    #pragma unroll
    for (int mi=0;mi<4;mi++)
    #pragma unroll
    for (int ni=0;ni<4;ni++){
        const int row0 = bm + wm*64 + mi*16 + gid;
        const int col0 = bn + wn*32 + ni*8 + t4*2;
        #pragma unroll
        for (int i=0;i<4;i++){
            const int row = row0 + ((i>=2)?8:0);
            const int col = col0 + (i&1);
            float v = acc[mi][ni][i] + bias[col];
            if (EPI == 1) v += res[(size_t)row*N + col];
            if (EPI == 2) v = 0.5f*v*(1.0f + erff(v*0.70710678118654752f));
            C[(size_t)row*N + col] = v;
        }
    }
}

// ---------------- attention scores: S[z,l,m] = 8 * sum_d q(b,l,h,d) k(b,m,h,d) ----------------
// split-tf32 (logit path must be ~fp32 accurate)
__global__ void __launch_bounds__(256) attn_score_k(
    const float* __restrict__ Q, const float* __restrict__ Kx, float* __restrict__ S)
{
    __shared__ float Qs[128*36];
    __shared__ float Ks[128*36];   // stored [m][d]
    const int tid  = threadIdx.x;
    const int z = blockIdx.z, b = z >> 4, h = z & 15;
    const int bm = blockIdx.y*128, bn = blockIdx.x*128;
    const int lane = tid & 31, warp = tid >> 5;
    const int wm = warp >> 2, wn = warp & 3;
    const int gid = lane >> 2, t4 = lane & 3;

    float acc[4][4][4];
    #pragma unroll
    for (int a=0;a<4;a++)
    #pragma unroll
    for (int c=0;c<4;c++)
    #pragma unroll
    for (int i=0;i<4;i++) acc[a][c][i] = 0.f;

    const int ar = tid >> 3, ac4 = tid & 7;
    const float* Qp = Q  + ((size_t)(b*LL_ + bm + ar)*HH_ + h)*DH_ + ac4*4;
    const float* Kp = Kx + ((size_t)(b*LL_ + bn + ar)*HH_ + h)*DH_ + ac4*4;

    #pragma unroll
    for (int kt = 0; kt < 2; kt++){
        float4 qr[4], kr[4];
        #pragma unroll
        for (int i=0;i<4;i++){
            qr[i] = *(const float4*)(Qp + kt*32 + (size_t)(32*i)*1024);
            kr[i] = *(const float4*)(Kp + kt*32 + (size_t)(32*i)*1024);
        }
        if (kt) __syncthreads();
        #pragma unroll
        for (int i=0;i<4;i++){
            *(float4*)(Qs + (ar+32*i)*36 + ac4*4) = qr[i];
            *(float4*)(Ks + (ar+32*i)*36 + ac4*4) = kr[i];
        }
        __syncthreads();
        #pragma unroll
        for (int ks=0;ks<4;ks++){
            uint32_t ah[4][4], al[4][4], bh[4][2], bl[4][2];
            #pragma unroll
            for (int mi=0;mi<4;mi++){
                const int r0 = (wm*64 + mi*16 + gid)*36 + ks*8 + t4;
                float x0 = Qs[r0], x1 = Qs[r0 + 8*36], x2 = Qs[r0 + 4], x3 = Qs[r0 + 8*36 + 4];
                ah[mi][0]=f2tf(x0); ah[mi][1]=f2tf(x1); ah[mi][2]=f2tf(x2); ah[mi][3]=f2tf(x3);
                al[mi][0]=f2tf(x0-__uint_as_float(ah[mi][0]));
                al[mi][1]=f2tf(x1-__uint_as_float(ah[mi][1]));
                al[mi][2]=f2tf(x2-__uint_as_float(ah[mi][2]));
                al[mi][3]=f2tf(x3-__uint_as_float(ah[mi][3]));
            }
            #pragma unroll
            for (int ni=0;ni<4;ni++){
                const int c0 = wn*32 + ni*8 + gid;
                float y0 = Ks[c0*36 + ks*8 + t4];
                float y1 = Ks[c0*36 + ks*8 + t4 + 4];
                bh[ni][0]=f2tf(y0); bh[ni][1]=f2tf(y1);
                bl[ni][0]=f2tf(y0-__uint_as_float(bh[ni][0]));
                bl[ni][1]=f2tf(y1-__uint_as_float(bh[ni][1]));
            }
            #pragma unroll
            for (int mi=0;mi<4;mi++)
            #pragma unroll
            for (int ni=0;ni<4;ni++){
                mma_tf32(acc[mi][ni], ah[mi], bh[ni]);
                mma_tf32(acc[mi][ni], ah[mi], bl[ni]);
                mma_tf32(acc[mi][ni], al[mi], bh[ni]);
            }
        }
    }

    float* Sz = S + (size_t)z*LL_*LL_;
    #pragma unroll
    for (int mi=0;mi<4;mi++)
    #pragma unroll
    for (int ni=0;ni<4;ni++){
        const int row0 = bm + wm*64 + mi*16 + gid;
        const int col0 = bn + wn*32 + ni*8 + t4*2;
        #pragma unroll
        for (int i=0;i<4;i++){
            const int row = row0 + ((i>=2)?8:0);
            const int col = col0 + (i&1);
            Sz[(size_t)row*LL_ + col] = 8.0f * acc[mi][ni][i];
        }
    }
}

// ---------------- row softmax over m (2048), in-place ----------------
__global__ void softmax_k(float* __restrict__ S)
{
    __shared__ float red[256];
    const int t = threadIdx.x;
    float4* row = (float4*)(S + (size_t)blockIdx.y*LL_*LL_ + (size_t)blockIdx.x*LL_);
    float4 v0 = row[t], v1 = row[t+256];
    float m = fmaxf(fmaxf(fmaxf(v0.x,v0.y), fmaxf(v0.z,v0.w)),
                    fmaxf(fmaxf(v1.x,v1.y), fmaxf(v1.z,v1.w)));
    red[t] = m; __syncthreads();
    #pragma unroll
    for (int s=128;s>0;s>>=1){ if (t<s) red[t] = fmaxf(red[t], red[t+s]); __syncthreads(); }
    m = red[0]; __syncthreads();
    v0.x = expf(v0.x-m); v0.y = expf(v0.y-m); v0.z = expf(v0.z-m); v0.w = expf(v0.w-m);
    v1.x = expf(v1.x-m); v1.y = expf(v1.y-m); v1.z = expf(v1.z-m); v1.w = expf(v1.w-m);
    red[t] = v0.x+v0.y+v0.z+v0.w + v1.x+v1.y+v1.z+v1.w;
    __syncthreads();
    #pragma unroll
    for (int s=128;s>0;s>>=1){ if (t<s) red[t] += red[t+s]; __syncthreads(); }
    const float inv = 1.0f / red[0];
    v0.x*=inv; v0.y*=inv; v0.z*=inv; v0.w*=inv;
    v1.x*=inv; v1.y*=inv; v1.z*=inv; v1.w*=inv;
    row[t] = v0; row[t+256] = v1;
}

// ---------------- ctx[b,l,h,d] = sum_m P[z,l,m] * v(b,m,h,d) ----------------
__global__ void __launch_bounds__(256) attn_av_k(
    const float* __restrict__ P, const float* __restrict__ V, float* __restrict__ Ctx)
{
    __shared__ float Ps[128*36];  // [l][m-chunk]
    __shared__ float Vs[32*72];   // [m-chunk][d]
    const int tid  = threadIdx.x;
    const int z = blockIdx.y, b = z >> 4, h = z & 15;
    const int bm = blockIdx.x*128;
    const int lane = tid & 31, warp = tid >> 5;
    const int wm = warp >> 1, wn = warp & 1;   // 4x2 warp grid, warp tile 32x32
    const int gid = lane >> 2, t4 = lane & 3;

    float acc[2][4][4];
    #pragma unroll
    for (int a=0;a<2;a++)
    #pragma unroll
    for (int c=0;c<4;c++)
    #pragma unroll
    for (int i=0;i<4;i++) acc[a][c][i] = 0.f;

    const int ar = tid >> 3, ac4 = tid & 7;    // P rows
    const int vr = tid >> 4, vc4 = tid & 15;   // V rows (16 f4 per 64-wide row)
    const float* Pp = P + (size_t)z*LL_*LL_ + (size_t)(bm+ar)*LL_ + ac4*4;
    const float* Vp = V + ((size_t)(b*LL_ + vr)*HH_ + h)*DH_ + vc4*4;

    float4 pR[4], vR[2];
    #pragma unroll
    for (int i=0;i<4;i++) pR[i] = *(const float4*)(Pp + (size_t)(32*i)*LL_);
    #pragma unroll
    for (int i=0;i<2;i++) vR[i] = *(const float4*)(Vp + (size_t)(16*i)*1024);

    const int KT = LL_/32;   // 64
    for (int t = 0; t < KT; t++){
        #pragma unroll
        for (int i=0;i<4;i++) *(float4*)(Ps + (ar+32*i)*36 + ac4*4) = pR[i];
        #pragma unroll
        for (int i=0;i<2;i++) *(float4*)(Vs + (vr+16*i)*72 + vc4*4) = vR[i];
        __syncthreads();
        if (t+1 < KT){
            const int k0 = (t+1)*32;
            #pragma unroll
            for (int i=0;i<4;i++) pR[i] = *(const float4*)(Pp + k0 + (size_t)(32*i)*LL_);
            #pragma unroll
            for (int i=0;i<2;i++) vR[i] = *(const float4*)(Vp + (size_t)(k0+16*i)*1024);
        }
        #pragma unroll
        for (int ks=0;ks<4;ks++){
            uint32_t a[2][4], bfr[4][2];
            #pragma unroll
            for (int mi=0;mi<2;mi++){
                const int r0 = (wm*32 + mi*16 + gid)*36 + ks*8 + t4;
                a[mi][0]=f2tf(Ps[r0]);        a[mi][1]=f2tf(Ps[r0 + 8*36]);
                a[mi][2]=f2tf(Ps[r0 + 4]);    a[mi][3]=f2tf(Ps[r0 + 8*36 + 4]);
            }
            #pragma unroll
            for (int ni=0;ni<4;ni++){
                const int c0 = wn*32 + ni*8 + gid;
                bfr[ni][0] = f2tf(Vs[(ks*8+t4)*72 + c0]);
                bfr[ni][1] = f2tf(Vs[(ks*8+t4+4)*72 + c0]);
            }
            #pragma unroll
            for (int mi=0;mi<2;mi++)
            #pragma unroll
            for (int ni=0;ni<4;ni++)
                mma_tf32(acc[mi][ni], a[mi], bfr[ni]);
        }
        __syncthreads();
    }

    #pragma unroll
    for (int mi=0;mi<2;mi++)
    #pragma unroll
    for (int ni=0;ni<4;ni++){
        const int row0 = bm + wm*32 + mi*16 + gid;
        const int col0 = wn*32 + ni*8 + t4*2;
        #pragma unroll
        for (int i=0;i<4;i++){
            const int row = row0 + ((i>=2)?8:0);
            const int col = col0 + (i&1);
            Ctx[((size_t)(b*LL_ + row)*HH_ + h)*DH_ + col] = acc[mi][ni][i];
        }
    }
}

// ---------------- launch ----------------
extern "C" void kernel_launch(void* const* d_in, const int* in_sizes, int n_in,
                              void* d_out, int out_size)
{
    const float* x     = (const float*)d_in[0];
    const float* ln1_w = (const float*)d_in[1];
    const float* ln1_b = (const float*)d_in[2];
    const float* wq    = (const float*)d_in[3];
    const float* bq    = (const float*)d_in[4];
    const float* wk    = (const float*)d_in[5];
    const float* bk    = (const float*)d_in[6];
    const float* wv    = (const float*)d_in[7];
    const float* bv    = (const float*)d_in[8];
    const float* wo    = (const float*)d_in[9];
    const float* bo    = (const float*)d_in[10];
    const float* ln2_w = (const float*)d_in[11];
    const float* ln2_b = (const float*)d_in[12];
    const float* wu    = (const float*)d_in[13];
    const float* bu    = (const float*)d_in[14];
    const float* wd    = (const float*)d_in[15];
    const float* bd    = (const float*)d_in[16];
    float* out = (float*)d_out;

    float *xn, *q, *k, *v, *ctx, *hidden, *hn, *up, *S;
    cudaGetSymbolAddress((void**)&xn,     g_xn);
    cudaGetSymbolAddress((void**)&q,      g_q);
    cudaGetSymbolAddress((void**)&k,      g_k);
    cudaGetSymbolAddress((void**)&v,      g_v);
    cudaGetSymbolAddress((void**)&ctx,    g_ctx);
    cudaGetSymbolAddress((void**)&hidden, g_hidden);
    cudaGetSymbolAddress((void**)&hn,     g_hn);
    cudaGetSymbolAddress((void**)&up,     g_up);
    cudaGetSymbolAddress((void**)&S,      g_S);

    const dim3 blk(256);
    const dim3 gE(EE_/128, NTOK/128);    // (8, 32)
    const dim3 gF(FF_/128, NTOK/128);    // (32, 32)

    // 1. LN1
    ln_k<<<NTOK, blk>>>(x, ln1_w, ln1_b, xn);
    // 2. Q, K (split-tf32), V (tf32)
    gemm_k<0, true ><<<gE, blk>>>(xn, wq, bq, nullptr, q, NTOK, EE_, EE_);
    gemm_k<0, true ><<<gE, blk>>>(xn, wk, bk, nullptr, k, NTOK, EE_, EE_);
    gemm_k<0, false><<<gE, blk>>>(xn, wv, bv, nullptr, v, NTOK, EE_, EE_);
    // 3. scores, softmax, context
    attn_score_k<<<dim3(LL_/128, LL_/128, NZ), blk>>>(q, k, S);
    softmax_k   <<<dim3(LL_, NZ), blk>>>(S);
    attn_av_k   <<<dim3(LL_/128, NZ), blk>>>(S, v, ctx);
    // 4. output proj + residual
    gemm_k<1, false><<<gE, blk>>>(ctx, wo, bo, x, hidden, NTOK, EE_, EE_);
    // 5. LN2 + FFN
    ln_k<<<NTOK, blk>>>(hidden, ln2_w, ln2_b, hn);
    gemm_k<2, false><<<gF, blk>>>(hn, wu, bu, nullptr, up, NTOK, FF_, EE_);
    gemm_k<1, false><<<gE, blk>>>(up, wd, bd, hidden, out, NTOK, EE_, FF_);
    (void)in_sizes; (void)n_in; (void)out_size;
}

// round 4
// speedup vs baseline: 1.0532x; 1.0532x over previous
#include <cuda_runtime.h>
#include <cstdint>
#include <cstdio>

// ---------------- problem constants ----------------
#define BB_   2
#define LL_   2048
#define EE_   1024
#define HH_   16
#define DH_   64
#define FF_   4096
#define NTOK  (BB_*LL_)          // 4096
#define NZ    (BB_*HH_)          // 32

// ---------------- scratch (device globals; no allocations allowed) ----------------
__device__ float g_xn[NTOK*EE_];
__device__ float g_q [NTOK*EE_];
__device__ float g_k [NTOK*EE_];
__device__ float g_v [NTOK*EE_];
__device__ float g_ctx[NTOK*EE_];
__device__ float g_hidden[NTOK*EE_];
__device__ float g_hn[NTOK*EE_];
__device__ float g_up[(size_t)NTOK*FF_];
__device__ float g_S[(size_t)NZ*LL_*LL_];   // 512 MB attention scores / probs

// ---------------- helpers ----------------
__device__ __forceinline__ uint32_t f2tf(float x){
    uint32_t r; asm("cvt.rna.tf32.f32 %0, %1;" : "=r"(r) : "f"(x)); return r;
}
__device__ __forceinline__ void mma_tf32(float c[4], const uint32_t a[4], const uint32_t b[2]){
    asm volatile("mma.sync.aligned.m16n8k8.row.col.f32.tf32.tf32.f32 "
        "{%0,%1,%2,%3},{%4,%5,%6,%7},{%8,%9},{%0,%1,%2,%3};"
        : "+f"(c[0]), "+f"(c[1]), "+f"(c[2]), "+f"(c[3])
        : "r"(a[0]), "r"(a[1]), "r"(a[2]), "r"(a[3]), "r"(b[0]), "r"(b[1]));
}
__device__ __forceinline__ void cp16(void* dst, const void* src){
    uint32_t d = (uint32_t)__cvta_generic_to_shared(dst);
    asm volatile("cp.async.cg.shared.global [%0], [%1], 16;" :: "r"(d), "l"(src));
}
__device__ __forceinline__ void cp_commit(){
    asm volatile("cp.async.commit_group;" ::: "memory");
}
template<int N>
__device__ __forceinline__ void cp_wait(){
    asm volatile("cp.async.wait_group %0;" :: "n"(N) : "memory");
}

// ---------------- LayerNorm: one block per token (E=1024, 256 thr x float4) ----------------
__global__ void ln_k(const float* __restrict__ X, const float* __restrict__ w,
                     const float* __restrict__ bb, float* __restrict__ O)
{
    __shared__ float red[256];
    const int t = threadIdx.x;
    const size_t off = (size_t)blockIdx.x * EE_;
    float4 v = *(const float4*)(X + off + t*4);
    red[t] = v.x + v.y + v.z + v.w;
    __syncthreads();
    #pragma unroll
    for (int s = 128; s > 0; s >>= 1){ if (t < s) red[t] += red[t+s]; __syncthreads(); }
    float mu = red[0] * (1.f/1024.f);
    __syncthreads();
    float d0 = v.x-mu, d1 = v.y-mu, d2 = v.z-mu, d3 = v.w-mu;
    red[t] = d0*d0 + d1*d1 + d2*d2 + d3*d3;
    __syncthreads();
    #pragma unroll
    for (int s = 128; s > 0; s >>= 1){ if (t < s) red[t] += red[t+s]; __syncthreads(); }
    float inv = rsqrtf(red[0] * (1.f/1024.f) + 1e-5f);
    float4 wv = *(const float4*)(w + t*4);
    float4 bv = *(const float4*)(bb + t*4);
    float4 o;
    o.x = d0*inv*wv.x + bv.x;  o.y = d1*inv*wv.y + bv.y;
    o.z = d2*inv*wv.z + bv.z;  o.w = d3*inv*wv.w + bv.w;
    *(float4*)(O + off + t*4) = o;
}

// ---------------- generic GEMM: C[M,N] = epi(A[M,K] @ W[K,N] + bias (+res)) ----------------
// EPI: 0 = bias, 1 = bias + residual, 2 = bias + exact GELU
// SPLIT: 2-term tf32 split (3 MMAs) for ~fp32 operand accuracy
// cp.async 2-stage pipeline, dynamic smem (2 x 35.3KB)
#define GSS 8832   // stage stride in floats: 128*36 + 32*132

template<int EPI, bool SPLIT, int MINB>
__global__ void __launch_bounds__(256, MINB) gemm_k(
    const float* __restrict__ A, const float* __restrict__ W,
    const float* __restrict__ bias, const float* __restrict__ res,
    float* __restrict__ C, int M, int N, int K)
{
    extern __shared__ float sm[];
    const int tid  = threadIdx.x;
    const int bm   = blockIdx.y*128, bn = blockIdx.x*128;
    const int lane = tid & 31, warp = tid >> 5;
    const int wm   = warp >> 2, wn = warp & 3;      // 2x4 warp grid, warp tile 64x32
    const int gid  = lane >> 2, t4 = lane & 3;

    float acc[4][4][4];
    #pragma unroll
    for (int a=0;a<4;a++)
    #pragma unroll
    for (int b=0;b<4;b++)
    #pragma unroll
    for (int c=0;c<4;c++) acc[a][b][c] = 0.f;

    const int ar = tid >> 3, ac4 = tid & 7;    // A: 4 float4 per thread
    const int br = tid >> 5, bc4 = tid & 31;   // B: 4 float4 per thread
    const float* Ap = A + (size_t)(bm+ar)*K + ac4*4;
    const float* Wp = W + (size_t)br*N + bn + bc4*4;
    const int KT = K >> 5;

    auto issue = [&](int t){
        const int s = t & 1;
        float* As = sm + s*GSS;
        float* Bs = As + 4608;
        const float* ap = Ap + t*32;
        const float* wp = Wp + (size_t)t*32*N;
        #pragma unroll
        for (int i=0;i<4;i++) cp16(As + (ar+32*i)*36 + ac4*4, ap + (size_t)(32*i)*K);
        #pragma unroll
        for (int i=0;i<4;i++) cp16(Bs + (br+8*i)*132 + bc4*4, wp + (size_t)(8*i)*N);
        cp_commit();
    };

    issue(0);
    for (int t = 0; t < KT; t++){
        if (t+1 < KT){ issue(t+1); cp_wait<1>(); }
        else         { cp_wait<0>(); }
        __syncthreads();
        const float* As = sm + (t&1)*GSS;
        const float* Bs = As + 4608;
        #pragma unroll
        for (int ks=0;ks<4;ks++){
            uint32_t ah[4][4], al[4][4], bh[4][2], bl[4][2];
            #pragma unroll
            for (int mi=0;mi<4;mi++){
                const int r0 = (wm*64 + mi*16 + gid)*36 + ks*8 + t4;
                float x0 = As[r0], x1 = As[r0 + 8*36], x2 = As[r0 + 4], x3 = As[r0 + 8*36 + 4];
                ah[mi][0]=f2tf(x0); ah[mi][1]=f2tf(x1); ah[mi][2]=f2tf(x2); ah[mi][3]=f2tf(x3);
                if (SPLIT){
                    al[mi][0]=f2tf(x0-__uint_as_float(ah[mi][0]));
                    al[mi][1]=f2tf(x1-__uint_as_float(ah[mi][1]));
                    al[mi][2]=f2tf(x2-__uint_as_float(ah[mi][2]));
                    al[mi][3]=f2tf(x3-__uint_as_float(ah[mi][3]));
                }
            }
            #pragma unroll
            for (int ni=0;ni<4;ni++){
                const int c0 = wn*32 + ni*8 + gid;
                float y0 = Bs[(ks*8+t4)*132 + c0];
                float y1 = Bs[(ks*8+t4+4)*132 + c0];
                bh[ni][0]=f2tf(y0); bh[ni][1]=f2tf(y1);
                if (SPLIT){
                    bl[ni][0]=f2tf(y0-__uint_as_float(bh[ni][0]));
                    bl[ni][1]=f2tf(y1-__uint_as_float(bh[ni][1]));
                }
            }
            #pragma unroll
            for (int mi=0;mi<4;mi++)
            #pragma unroll
            for (int ni=0;ni<4;ni++){
                mma_tf32(acc[mi][ni], ah[mi], bh[ni]);
                if (SPLIT){
                    mma_tf32(acc[mi][ni], ah[mi], bl[ni]);
                    mma_tf32(acc[mi][ni], al[mi], bh[ni]);
                }
            }
        }
        __syncthreads();
    }

    #pragma unroll
    for (int mi=0;mi<4;mi++)
    #pragma unroll
    for (int ni=0;ni<4;ni++){
        const int row0 = bm + wm*64 + mi*16 + gid;
        const int col0 = bn + wn*32 + ni*8 + t4*2;
        #pragma unroll
        for (int i=0;i<4;i++){
            const int row = row0 + ((i>=2)?8:0);
            const int col = col0 + (i&1);
            float v = acc[mi][ni][i] + bias[col];
            if (EPI == 1) v += res[(size_t)row*N + col];
            if (EPI == 2) v = 0.5f*v*(1.0f + erff(v*0.70710678118654752f));
            C[(size_t)row*N + col] = v;
        }
    }
}

// ---------------- attention scores: S[z,l,m] = 8 * sum_d q(b,l,h,d) k(b,m,h,d) ----------------
// split-tf32 (logit path must be ~fp32 accurate)
__global__ void __launch_bounds__(256) attn_score_k(
    const float* __restrict__ Q, const float* __restrict__ Kx, float* __restrict__ S)
{
    __shared__ float Qs[128*36];
    __shared__ float Ks[128*36];   // stored [m][d]
    const int tid  = threadIdx.x;
    const int z = blockIdx.z, b = z >> 4, h = z & 15;
    const int bm = blockIdx.y*128, bn = blockIdx.x*128;
    const int lane = tid & 31, warp = tid >> 5;
    const int wm = warp >> 2, wn = warp & 3;
    const int gid = lane >> 2, t4 = lane & 3;

    float acc[4][4][4];
    #pragma unroll
    for (int a=0;a<4;a++)
    #pragma unroll
    for (int c=0;c<4;c++)
    #pragma unroll
    for (int i=0;i<4;i++) acc[a][c][i] = 0.f;

    const int ar = tid >> 3, ac4 = tid & 7;
    const float* Qp = Q  + ((size_t)(b*LL_ + bm + ar)*HH_ + h)*DH_ + ac4*4;
    const float* Kp = Kx + ((size_t)(b*LL_ + bn + ar)*HH_ + h)*DH_ + ac4*4;

    #pragma unroll
    for (int kt = 0; kt < 2; kt++){
        float4 qr[4], kr[4];
        #pragma unroll
        for (int i=0;i<4;i++){
            qr[i] = *(const float4*)(Qp + kt*32 + (size_t)(32*i)*1024);
            kr[i] = *(const float4*)(Kp + kt*32 + (size_t)(32*i)*1024);
        }
        if (kt) __syncthreads();
        #pragma unroll
        for (int i=0;i<4;i++){
            *(float4*)(Qs + (ar+32*i)*36 + ac4*4) = qr[i];
            *(float4*)(Ks + (ar+32*i)*36 + ac4*4) = kr[i];
        }
        __syncthreads();
        #pragma unroll
        for (int ks=0;ks<4;ks++){
            uint32_t ah[4][4], al[4][4], bh[4][2], bl[4][2];
            #pragma unroll
            for (int mi=0;mi<4;mi++){
                const int r0 = (wm*64 + mi*16 + gid)*36 + ks*8 + t4;
                float x0 = Qs[r0], x1 = Qs[r0 + 8*36], x2 = Qs[r0 + 4], x3 = Qs[r0 + 8*36 + 4];
                ah[mi][0]=f2tf(x0); ah[mi][1]=f2tf(x1); ah[mi][2]=f2tf(x2); ah[mi][3]=f2tf(x3);
                al[mi][0]=f2tf(x0-__uint_as_float(ah[mi][0]));
                al[mi][1]=f2tf(x1-__uint_as_float(ah[mi][1]));
                al[mi][2]=f2tf(x2-__uint_as_float(ah[mi][2]));
                al[mi][3]=f2tf(x3-__uint_as_float(ah[mi][3]));
            }
            #pragma unroll
            for (int ni=0;ni<4;ni++){
                const int c0 = wn*32 + ni*8 + gid;
                float y0 = Ks[c0*36 + ks*8 + t4];
                float y1 = Ks[c0*36 + ks*8 + t4 + 4];
                bh[ni][0]=f2tf(y0); bh[ni][1]=f2tf(y1);
                bl[ni][0]=f2tf(y0-__uint_as_float(bh[ni][0]));
                bl[ni][1]=f2tf(y1-__uint_as_float(bh[ni][1]));
            }
            #pragma unroll
            for (int mi=0;mi<4;mi++)
            #pragma unroll
            for (int ni=0;ni<4;ni++){
                mma_tf32(acc[mi][ni], ah[mi], bh[ni]);
                mma_tf32(acc[mi][ni], ah[mi], bl[ni]);
                mma_tf32(acc[mi][ni], al[mi], bh[ni]);
            }
        }
    }

    float* Sz = S + (size_t)z*LL_*LL_;
    #pragma unroll
    for (int mi=0;mi<4;mi++)
    #pragma unroll
    for (int ni=0;ni<4;ni++){
        const int row0 = bm + wm*64 + mi*16 + gid;
        const int col0 = bn + wn*32 + ni*8 + t4*2;
        #pragma unroll
        for (int i=0;i<4;i++){
            const int row = row0 + ((i>=2)?8:0);
            const int col = col0 + (i&1);
            Sz[(size_t)row*LL_ + col] = 8.0f * acc[mi][ni][i];
        }
    }
}

// ---------------- row softmax over m (2048), in-place ----------------
__global__ void softmax_k(float* __restrict__ S)
{
    __shared__ float red[256];
    const int t = threadIdx.x;
    float4* row = (float4*)(S + (size_t)blockIdx.y*LL_*LL_ + (size_t)blockIdx.x*LL_);
    float4 v0 = row[t], v1 = row[t+256];
    float m = fmaxf(fmaxf(fmaxf(v0.x,v0.y), fmaxf(v0.z,v0.w)),
                    fmaxf(fmaxf(v1.x,v1.y), fmaxf(v1.z,v1.w)));
    red[t] = m; __syncthreads();
    #pragma unroll
    for (int s=128;s>0;s>>=1){ if (t<s) red[t] = fmaxf(red[t], red[t+s]); __syncthreads(); }
    m = red[0]; __syncthreads();
    v0.x = expf(v0.x-m); v0.y = expf(v0.y-m); v0.z = expf(v0.z-m); v0.w = expf(v0.w-m);
    v1.x = expf(v1.x-m); v1.y = expf(v1.y-m); v1.z = expf(v1.z-m); v1.w = expf(v1.w-m);
    red[t] = v0.x+v0.y+v0.z+v0.w + v1.x+v1.y+v1.z+v1.w;
    __syncthreads();
    #pragma unroll
    for (int s=128;s>0;s>>=1){ if (t<s) red[t] += red[t+s]; __syncthreads(); }
    const float inv = 1.0f / red[0];
    v0.x*=inv; v0.y*=inv; v0.z*=inv; v0.w*=inv;
    v1.x*=inv; v1.y*=inv; v1.z*=inv; v1.w*=inv;
    row[t] = v0; row[t+256] = v1;
}

// ---------------- ctx[b,l,h,d] = sum_m P[z,l,m] * v(b,m,h,d) ----------------
// cp.async 2-stage pipeline, dynamic smem (2 x 27.6KB)
#define VSS 6912   // stage stride in floats: 128*36 + 32*72

__global__ void __launch_bounds__(256, 2) attn_av_k(
    const float* __restrict__ P, const float* __restrict__ V, float* __restrict__ Ctx)
{
    extern __shared__ float sm[];
    const int tid  = threadIdx.x;
    const int z = blockIdx.y, b = z >> 4, h = z & 15;
    const int bm = blockIdx.x*128;
    const int lane = tid & 31, warp = tid >> 5;
    const int wm = warp >> 1, wn = warp & 1;   // 4x2 warp grid, warp tile 32x32
    const int gid = lane >> 2, t4 = lane & 3;

    float acc[2][4][4];
    #pragma unroll
    for (int a=0;a<2;a++)
    #pragma unroll
    for (int c=0;c<4;c++)
    #pragma unroll
    for (int i=0;i<4;i++) acc[a][c][i] = 0.f;

    const int ar = tid >> 3, ac4 = tid & 7;    // P rows
    const int vr = tid >> 4, vc4 = tid & 15;   // V rows (16 f4 per 64-wide row)
    const float* Pp = P + (size_t)z*LL_*LL_ + (size_t)(bm+ar)*LL_ + ac4*4;
    const float* Vp = V + ((size_t)(b*LL_ + vr)*HH_ + h)*DH_ + vc4*4;

    const int KT = LL_/32;   // 64

    auto issue = [&](int t){
        const int s = t & 1;
        float* Ps = sm + s*VSS;
        float* Vs = Ps + 4608;
        const int k0 = t*32;
        #pragma unroll
        for (int i=0;i<4;i++) cp16(Ps + (ar+32*i)*36 + ac4*4, Pp + k0 + (size_t)(32*i)*LL_);
        #pragma unroll
        for (int i=0;i<2;i++) cp16(Vs + (vr+16*i)*72 + vc4*4, Vp + (size_t)(k0+16*i)*1024);
        cp_commit();
    };

    issue(0);
    for (int t = 0; t < KT; t++){
        if (t+1 < KT){ issue(t+1); cp_wait<1>(); }
        else         { cp_wait<0>(); }
        __syncthreads();
        const float* Ps = sm + (t&1)*VSS;
        const float* Vs = Ps + 4608;
        #pragma unroll
        for (int ks=0;ks<4;ks++){
            uint32_t a[2][4], bfr[4][2];
            #pragma unroll
            for (int mi=0;mi<2;mi++){
                const int r0 = (wm*32 + mi*16 + gid)*36 + ks*8 + t4;
                a[mi][0]=f2tf(Ps[r0]);        a[mi][1]=f2tf(Ps[r0 + 8*36]);
                a[mi][2]=f2tf(Ps[r0 + 4]);    a[mi][3]=f2tf(Ps[r0 + 8*36 + 4]);
            }
            #pragma unroll
            for (int ni=0;ni<4;ni++){
                const int c0 = wn*32 + ni*8 + gid;
                bfr[ni][0] = f2tf(Vs[(ks*8+t4)*72 + c0]);
                bfr[ni][1] = f2tf(Vs[(ks*8+t4+4)*72 + c0]);
            }
            #pragma unroll
            for (int mi=0;mi<2;mi++)
            #pragma unroll
            for (int ni=0;ni<4;ni++)
                mma_tf32(acc[mi][ni], a[mi], bfr[ni]);
        }
        __syncthreads();
    }

    #pragma unroll
    for (int mi=0;mi<2;mi++)
    #pragma unroll
    for (int ni=0;ni<4;ni++){
        const int row0 = bm + wm*32 + mi*16 + gid;
        const int col0 = wn*32 + ni*8 + t4*2;
        #pragma unroll
        for (int i=0;i<4;i++){
            const int row = row0 + ((i>=2)?8:0);
            const int col = col0 + (i&1);
            Ctx[((size_t)(b*LL_ + row)*HH_ + h)*DH_ + col] = acc[mi][ni][i];
        }
    }
}

// ---------------- launch ----------------
extern "C" void kernel_launch(void* const* d_in, const int* in_sizes, int n_in,
                              void* d_out, int out_size)
{
    const float* x     = (const float*)d_in[0];
    const float* ln1_w = (const float*)d_in[1];
    const float* ln1_b = (const float*)d_in[2];
    const float* wq    = (const float*)d_in[3];
    const float* bq    = (const float*)d_in[4];
    const float* wk    = (const float*)d_in[5];
    const float* bk    = (const float*)d_in[6];
    const float* wv    = (const float*)d_in[7];
    const float* bv    = (const float*)d_in[8];
    const float* wo    = (const float*)d_in[9];
    const float* bo    = (const float*)d_in[10];
    const float* ln2_w = (const float*)d_in[11];
    const float* ln2_b = (const float*)d_in[12];
    const float* wu    = (const float*)d_in[13];
    const float* bu    = (const float*)d_in[14];
    const float* wd    = (const float*)d_in[15];
    const float* bd    = (const float*)d_in[16];
    float* out = (float*)d_out;

    float *xn, *q, *k, *v, *ctx, *hidden, *hn, *up, *S;
    cudaGetSymbolAddress((void**)&xn,     g_xn);
    cudaGetSymbolAddress((void**)&q,      g_q);
    cudaGetSymbolAddress((void**)&k,      g_k);
    cudaGetSymbolAddress((void**)&v,      g_v);
    cudaGetSymbolAddress((void**)&ctx,    g_ctx);
    cudaGetSymbolAddress((void**)&hidden, g_hidden);
    cudaGetSymbolAddress((void**)&hn,     g_hn);
    cudaGetSymbolAddress((void**)&up,     g_up);
    cudaGetSymbolAddress((void**)&S,      g_S);

    const int GEMM_SMEM = 2*GSS*4;   // 70656 B
    const int AV_SMEM   = 2*VSS*4;   // 55296 B
    cudaFuncSetAttribute(gemm_k<0,true ,1>, cudaFuncAttributeMaxDynamicSharedMemorySize, GEMM_SMEM);
    cudaFuncSetAttribute(gemm_k<0,false,2>, cudaFuncAttributeMaxDynamicSharedMemorySize, GEMM_SMEM);
    cudaFuncSetAttribute(gemm_k<1,false,2>, cudaFuncAttributeMaxDynamicSharedMemorySize, GEMM_SMEM);
    cudaFuncSetAttribute(gemm_k<2,false,2>, cudaFuncAttributeMaxDynamicSharedMemorySize, GEMM_SMEM);
    cudaFuncSetAttribute(attn_av_k,         cudaFuncAttributeMaxDynamicSharedMemorySize, AV_SMEM);

    const dim3 blk(256);
    const dim3 gE(EE_/128, NTOK/128);    // (8, 32)
    const dim3 gF(FF_/128, NTOK/128);    // (32, 32)

    // 1. LN1
    ln_k<<<NTOK, blk>>>(x, ln1_w, ln1_b, xn);
    // 2. Q, K (split-tf32), V (tf32)
    gemm_k<0, true ,1><<<gE, blk, GEMM_SMEM>>>(xn, wq, bq, nullptr, q, NTOK, EE_, EE_);
    gemm_k<0, true ,1><<<gE, blk, GEMM_SMEM>>>(xn, wk, bk, nullptr, k, NTOK, EE_, EE_);
    gemm_k<0, false,2><<<gE, blk, GEMM_SMEM>>>(xn, wv, bv, nullptr, v, NTOK, EE_, EE_);
    // 3. scores, softmax, context
    attn_score_k<<<dim3(LL_/128, LL_/128, NZ), blk>>>(q, k, S);
    softmax_k   <<<dim3(LL_, NZ), blk>>>(S);
    attn_av_k   <<<dim3(LL_/128, NZ), blk, AV_SMEM>>>(S, v, ctx);
    // 4. output proj + residual
    gemm_k<1, false,2><<<gE, blk, GEMM_SMEM>>>(ctx, wo, bo, x, hidden, NTOK, EE_, EE_);
    // 5. LN2 + FFN
    ln_k<<<NTOK, blk>>>(hidden, ln2_w, ln2_b, hn);
    gemm_k<2, false,2><<<gF, blk, GEMM_SMEM>>>(hn, wu, bu, nullptr, up, NTOK, FF_, EE_);
    gemm_k<1, false,2><<<gE, blk, GEMM_SMEM>>>(up, wd, bd, hidden, out, NTOK, EE_, FF_);
    (void)in_sizes; (void)n_in; (void)out_size;
}